// round 1
// baseline (speedup 1.0000x reference)
#include <cuda_runtime.h>
#include <cstdint>

#define N_NODES   100000
#define N_EDGES   1600000
#define N_ETYPES  3
#define IN_FEATS  128
#define HEADS     4
#define OUT_FEATS 16
#define HD        64          // HEADS*OUT_FEATS (floats per node feat row)
#define NEG_SLOPE 0.2f

// ---------------- device scratch (static globals; no allocation) -------------
__device__ float4   g_feat[N_NODES * 16];   // [N][64] as 16 x float4 per node (25.6 MB)
__device__ float4   g_el[N_NODES];          // [N][4]
__device__ float4   g_er[N_NODES];          // [N][4]
__device__ unsigned g_m[N_NODES * 4];       // flipped-uint running max, init 0 == -inf
__device__ float4   g_z[N_NODES];           // softmax denominator per (node, head)
__device__ float4   g_ee[N_ETYPES];         // per-etype edge attention term [3][4]

// monotone order-preserving float<->uint mapping for atomicMax on floats
__device__ __forceinline__ unsigned fflip(float f) {
    unsigned u = __float_as_uint(f);
    return (u & 0x80000000u) ? ~u : (u | 0x80000000u);
}
__device__ __forceinline__ float funflip(unsigned u) {
    return __uint_as_float((u & 0x80000000u) ? (u ^ 0x80000000u) : ~u);
}

__device__ __forceinline__ void red_add_v4(float* addr, float a, float b, float c, float d) {
    asm volatile("red.global.add.v4.f32 [%0], {%1,%2,%3,%4};"
                 :: "l"(addr), "f"(a), "f"(b), "f"(c), "f"(d) : "memory");
}

// ---------------- init: zero rst region, max, denom ------------------------
__global__ void k_init(float* __restrict__ rst) {
    int i = blockIdx.x * 256 + threadIdx.x;
    if (i < N_NODES * HD) rst[i] = 0.0f;
    if (i < N_NODES * 4) {
        g_m[i] = 0u;                    // flipped(-inf) lower bound
        ((float*)g_z)[i] = 0.0f;
    }
}

// ---------------- tiny: per-etype edge term ee[t][h] ------------------------
__global__ void k_ee(const float* __restrict__ W_e, const float* __restrict__ attn_e,
                     const float* __restrict__ edge_emb) {
    int w = threadIdx.x >> 5, lane = threadIdx.x & 31;
    if (w >= N_ETYPES * HEADS) return;
    int t = w >> 2, h = w & 3;
    float acc = 0.0f;
#pragma unroll
    for (int ei = 0; ei < 2; ei++) {
        int e = lane + ei * 32;
        float dot = 0.0f;
#pragma unroll 8
        for (int k = 0; k < 64; k++)
            dot += edge_emb[t * 64 + k] * W_e[k * 256 + h * 64 + e];
        acc += dot * attn_e[h * 64 + e];
    }
#pragma unroll
    for (int o = 16; o; o >>= 1) acc += __shfl_xor_sync(0xffffffffu, acc, o);
    if (lane == 0) ((float*)g_ee)[t * 4 + h] = acc;
}

// ---------------- GEMM: feat = x @ W  (+ fused el/er epilogue) --------------
// 64 rows x 64 cols per block, 256 threads, 4x4 microtile, K tiled by 32.
__global__ __launch_bounds__(256) void k_gemm(const float* __restrict__ x,
                                              const float* __restrict__ W,
                                              const float* __restrict__ attn_l,
                                              const float* __restrict__ attn_r) {
    __shared__ float As[32][68];   // transposed A tile, padded
    __shared__ float Bs[32][64];
    int tid = threadIdx.x;
    int tx = tid & 15, ty = tid >> 4;
    int rb = blockIdx.x * 64;
    float acc[4][4] = {};

    for (int k0 = 0; k0 < IN_FEATS; k0 += 32) {
#pragma unroll
        for (int i = 0; i < 2; i++) {
            int f   = tid + 256 * i;      // float4 slot 0..511
            int row = f >> 3;             // 0..63
            int kq  = f & 7;              // k = kq*4
            float4 v = make_float4(0.f, 0.f, 0.f, 0.f);
            int gr = rb + row;
            if (gr < N_NODES) v = *(const float4*)&x[(long)gr * IN_FEATS + k0 + kq * 4];
            As[kq * 4 + 0][row] = v.x; As[kq * 4 + 1][row] = v.y;
            As[kq * 4 + 2][row] = v.z; As[kq * 4 + 3][row] = v.w;
        }
#pragma unroll
        for (int i = 0; i < 2; i++) {
            int f = tid + 256 * i;
            int k = f >> 4, c4 = f & 15;
            *(float4*)&Bs[k][c4 * 4] = *(const float4*)&W[(k0 + k) * HD + c4 * 4];
        }
        __syncthreads();
#pragma unroll
        for (int k = 0; k < 32; k++) {
            float4 a4 = *(float4*)&As[k][ty * 4];
            float4 b4 = *(float4*)&Bs[k][tx * 4];
            acc[0][0] += a4.x * b4.x; acc[0][1] += a4.x * b4.y; acc[0][2] += a4.x * b4.z; acc[0][3] += a4.x * b4.w;
            acc[1][0] += a4.y * b4.x; acc[1][1] += a4.y * b4.y; acc[1][2] += a4.y * b4.z; acc[1][3] += a4.y * b4.w;
            acc[2][0] += a4.z * b4.x; acc[2][1] += a4.z * b4.y; acc[2][2] += a4.z * b4.z; acc[2][3] += a4.z * b4.w;
            acc[3][0] += a4.w * b4.x; acc[3][1] += a4.w * b4.y; acc[3][2] += a4.w * b4.z; acc[3][3] += a4.w * b4.w;
        }
        __syncthreads();
    }

    // epilogue: feat store + el/er partial dots reduced over the 4 tx of each head
    int h = tx >> 2;
    float4 al = ((const float4*)attn_l)[h * 4 + (tx & 3)];
    float4 ar = ((const float4*)attn_r)[h * 4 + (tx & 3)];
#pragma unroll
    for (int i = 0; i < 4; i++) {
        int r = rb + ty * 4 + i;
        float4 o = make_float4(acc[i][0], acc[i][1], acc[i][2], acc[i][3]);
        float lp = o.x * al.x + o.y * al.y + o.z * al.z + o.w * al.w;
        float rp = o.x * ar.x + o.y * ar.y + o.z * ar.z + o.w * ar.w;
        lp += __shfl_xor_sync(0xffffffffu, lp, 1);
        lp += __shfl_xor_sync(0xffffffffu, lp, 2);
        rp += __shfl_xor_sync(0xffffffffu, rp, 1);
        rp += __shfl_xor_sync(0xffffffffu, rp, 2);
        if (r < N_NODES) {
            g_feat[(long)r * 16 + tx] = o;
            if ((tx & 3) == 0) {
                ((float*)g_el)[r * 4 + h] = lp;
                ((float*)g_er)[r * 4 + h] = rp;
            }
        }
    }
}

// recompute pre-softmax score for one edge (all 4 heads)
__device__ __forceinline__ float4 edge_score(int s, int d, int t) {
    float4 el = g_el[s], er = g_er[d], ee = g_ee[t];
    float4 v;
    v.x = el.x + er.x + ee.x;
    v.y = el.y + er.y + ee.y;
    v.z = el.z + er.z + ee.z;
    v.w = el.w + er.w + ee.w;
    v.x = v.x > 0.f ? v.x : NEG_SLOPE * v.x;
    v.y = v.y > 0.f ? v.y : NEG_SLOPE * v.y;
    v.z = v.z > 0.f ? v.z : NEG_SLOPE * v.z;
    v.w = v.w > 0.f ? v.w : NEG_SLOPE * v.w;
    return v;
}

// ---------------- pass 1: segment max over dst ------------------------------
__global__ __launch_bounds__(256) void k_max(const int* __restrict__ src,
                                             const int* __restrict__ dst,
                                             const int* __restrict__ et) {
    int i = blockIdx.x * 256 + threadIdx.x;
    if (i >= N_EDGES) return;
    int d = dst[i];
    float4 s = edge_score(src[i], d, et[i]);
    atomicMax(&g_m[d * 4 + 0], fflip(s.x));
    atomicMax(&g_m[d * 4 + 1], fflip(s.y));
    atomicMax(&g_m[d * 4 + 2], fflip(s.z));
    atomicMax(&g_m[d * 4 + 3], fflip(s.w));
}

// ---------------- pass 2: exp + segment sum ---------------------------------
__global__ __launch_bounds__(256) void k_sum(const int* __restrict__ src,
                                             const int* __restrict__ dst,
                                             const int* __restrict__ et) {
    int i = blockIdx.x * 256 + threadIdx.x;
    if (i >= N_EDGES) return;
    int d = dst[i];
    float4 s = edge_score(src[i], d, et[i]);
    uint4 mu = ((const uint4*)g_m)[d];
    float ex = expf(s.x - funflip(mu.x));
    float ey = expf(s.y - funflip(mu.y));
    float ez = expf(s.z - funflip(mu.z));
    float ew = expf(s.w - funflip(mu.w));
    red_add_v4((float*)&g_z[d], ex, ey, ez, ew);
}

// ---------------- pass 3: normalize + write a + aggregate rst ---------------
__global__ __launch_bounds__(256) void k_final(const int* __restrict__ src,
                                               const int* __restrict__ dst,
                                               const int* __restrict__ et,
                                               float* __restrict__ rst,
                                               float4* __restrict__ out_a) {
    int i = blockIdx.x * 256 + threadIdx.x;
    if (i >= N_EDGES) return;
    int sidx = src[i];
    int d = dst[i];
    float4 s = edge_score(sidx, d, et[i]);
    uint4 mu = ((const uint4*)g_m)[d];
    float4 z = g_z[d];
    float4 a;
    a.x = expf(s.x - funflip(mu.x)) / z.x;
    a.y = expf(s.y - funflip(mu.y)) / z.y;
    a.z = expf(s.z - funflip(mu.z)) / z.z;
    a.w = expf(s.w - funflip(mu.w)) / z.w;
    out_a[i] = a;

    const float4* fs = &g_feat[(long)sidx * 16];
    float* rbase = rst + (long)d * HD;
    float aa[4] = {a.x, a.y, a.z, a.w};
#pragma unroll
    for (int c = 0; c < 16; c++) {
        float4 f = fs[c];
        float av = aa[c >> 2];
        red_add_v4(rbase + c * 4, f.x * av, f.y * av, f.z * av, f.w * av);
    }
}

// ---------------- launch -----------------------------------------------------
extern "C" void kernel_launch(void* const* d_in, const int* in_sizes, int n_in,
                              void* d_out, int out_size) {
    const float* x        = (const float*)d_in[0];
    const float* W        = (const float*)d_in[1];
    const float* W_e      = (const float*)d_in[2];
    const float* attn_l   = (const float*)d_in[3];
    const float* attn_r   = (const float*)d_in[4];
    const float* attn_e   = (const float*)d_in[5];
    const float* edge_emb = (const float*)d_in[6];
    const int*   src      = (const int*)d_in[7];
    const int*   dst      = (const int*)d_in[8];
    const int*   et       = (const int*)d_in[9];

    float*  rst   = (float*)d_out;                       // [N, H, D] first
    float4* out_a = (float4*)(rst + (long)N_NODES * HD); // [E, H] second

    k_init<<<(N_NODES * HD + 255) / 256, 256>>>(rst);
    k_ee<<<1, 384>>>(W_e, attn_e, edge_emb);
    k_gemm<<<(N_NODES + 63) / 64, 256>>>(x, W, attn_l, attn_r);
    int eb = (N_EDGES + 255) / 256;
    k_max<<<eb, 256>>>(src, dst, et);
    k_sum<<<eb, 256>>>(src, dst, et);
    k_final<<<eb, 256>>>(src, dst, et, rst, out_a);
}

// round 2
// speedup vs baseline: 2.9009x; 2.9009x over previous
#include <cuda_runtime.h>
#include <cstdint>

#define N_NODES   100000
#define N_EDGES   1600000
#define N_ETYPES  3
#define IN_FEATS  128
#define HEADS     4
#define OUT_FEATS 16
#define HD        64
#define NEG_SLOPE 0.2f
#define SCAN_B    1024
#define NB        ((N_NODES + SCAN_B - 1) / SCAN_B)   // 98

// ---------------- device scratch (static globals; no allocation) -------------
__device__ float4 g_feat[N_NODES * 16];   // [N][64] as 16 x float4 (25.6 MB)
__device__ float4 g_el[N_NODES];          // [N][4]
__device__ float4 g_er[N_NODES];          // [N][4]
__device__ float4 g_ee[N_ETYPES];         // [3][4]
__device__ int    g_cnt[N_NODES];
__device__ int    g_incl[N_NODES];
__device__ int    g_bsum[NB];
__device__ int    g_boff[NB];
__device__ int    g_rowptr[N_NODES + 1];
__device__ int    g_cur[N_NODES];
__device__ int2   g_es[N_EDGES];          // sorted: {src, orig_id*4 | etype}

// ---------------- init: zero histogram --------------------------------------
__global__ void k_init() {
    int i = blockIdx.x * 256 + threadIdx.x;
    if (i < N_NODES) g_cnt[i] = 0;
}

// ---------------- per-etype edge term ee[t][h] -------------------------------
__global__ void k_ee(const float* __restrict__ W_e, const float* __restrict__ attn_e,
                     const float* __restrict__ edge_emb) {
    int w = threadIdx.x >> 5, lane = threadIdx.x & 31;
    if (w >= N_ETYPES * HEADS) return;
    int t = w >> 2, h = w & 3;
    float acc = 0.0f;
#pragma unroll
    for (int ei = 0; ei < 2; ei++) {
        int e = lane + ei * 32;
        float dot = 0.0f;
#pragma unroll 8
        for (int k = 0; k < 64; k++)
            dot += edge_emb[t * 64 + k] * W_e[k * 256 + h * 64 + e];
        acc += dot * attn_e[h * 64 + e];
    }
#pragma unroll
    for (int o = 16; o; o >>= 1) acc += __shfl_xor_sync(0xffffffffu, acc, o);
    if (lane == 0) ((float*)g_ee)[t * 4 + h] = acc;
}

// ---------------- GEMM: feat = x @ W  (+ fused el/er epilogue) ---------------
__global__ __launch_bounds__(256) void k_gemm(const float* __restrict__ x,
                                              const float* __restrict__ W,
                                              const float* __restrict__ attn_l,
                                              const float* __restrict__ attn_r) {
    __shared__ float As[32][68];
    __shared__ float Bs[32][64];
    int tid = threadIdx.x;
    int tx = tid & 15, ty = tid >> 4;
    int rb = blockIdx.x * 64;
    float acc[4][4] = {};

    for (int k0 = 0; k0 < IN_FEATS; k0 += 32) {
#pragma unroll
        for (int i = 0; i < 2; i++) {
            int f = tid + 256 * i;
            int row = f >> 3, kq = f & 7;
            float4 v = make_float4(0.f, 0.f, 0.f, 0.f);
            int gr = rb + row;
            if (gr < N_NODES) v = *(const float4*)&x[(long)gr * IN_FEATS + k0 + kq * 4];
            As[kq * 4 + 0][row] = v.x; As[kq * 4 + 1][row] = v.y;
            As[kq * 4 + 2][row] = v.z; As[kq * 4 + 3][row] = v.w;
        }
#pragma unroll
        for (int i = 0; i < 2; i++) {
            int f = tid + 256 * i;
            int k = f >> 4, c4 = f & 15;
            *(float4*)&Bs[k][c4 * 4] = *(const float4*)&W[(k0 + k) * HD + c4 * 4];
        }
        __syncthreads();
#pragma unroll
        for (int k = 0; k < 32; k++) {
            float4 a4 = *(float4*)&As[k][ty * 4];
            float4 b4 = *(float4*)&Bs[k][tx * 4];
            acc[0][0] += a4.x * b4.x; acc[0][1] += a4.x * b4.y; acc[0][2] += a4.x * b4.z; acc[0][3] += a4.x * b4.w;
            acc[1][0] += a4.y * b4.x; acc[1][1] += a4.y * b4.y; acc[1][2] += a4.y * b4.z; acc[1][3] += a4.y * b4.w;
            acc[2][0] += a4.z * b4.x; acc[2][1] += a4.z * b4.y; acc[2][2] += a4.z * b4.z; acc[2][3] += a4.z * b4.w;
            acc[3][0] += a4.w * b4.x; acc[3][1] += a4.w * b4.y; acc[3][2] += a4.w * b4.z; acc[3][3] += a4.w * b4.w;
        }
        __syncthreads();
    }

    int h = tx >> 2;
    float4 al = ((const float4*)attn_l)[h * 4 + (tx & 3)];
    float4 ar = ((const float4*)attn_r)[h * 4 + (tx & 3)];
#pragma unroll
    for (int i = 0; i < 4; i++) {
        int r = rb + ty * 4 + i;
        float4 o = make_float4(acc[i][0], acc[i][1], acc[i][2], acc[i][3]);
        float lp = o.x * al.x + o.y * al.y + o.z * al.z + o.w * al.w;
        float rp = o.x * ar.x + o.y * ar.y + o.z * ar.z + o.w * ar.w;
        lp += __shfl_xor_sync(0xffffffffu, lp, 1);
        lp += __shfl_xor_sync(0xffffffffu, lp, 2);
        rp += __shfl_xor_sync(0xffffffffu, rp, 1);
        rp += __shfl_xor_sync(0xffffffffu, rp, 2);
        if (r < N_NODES) {
            g_feat[(long)r * 16 + tx] = o;
            if ((tx & 3) == 0) {
                ((float*)g_el)[r * 4 + h] = lp;
                ((float*)g_er)[r * 4 + h] = rp;
            }
        }
    }
}

// ---------------- counting sort by dst ---------------------------------------
__global__ __launch_bounds__(256) void k_hist(const int* __restrict__ dst) {
    int i = blockIdx.x * 256 + threadIdx.x;
    if (i < N_EDGES) atomicAdd(&g_cnt[dst[i]], 1);
}

__global__ __launch_bounds__(SCAN_B) void k_scan1() {
    __shared__ int sh[SCAN_B];
    int b = blockIdx.x, t = threadIdx.x;
    int i = b * SCAN_B + t;
    sh[t] = (i < N_NODES) ? g_cnt[i] : 0;
#pragma unroll
    for (int o = 1; o < SCAN_B; o <<= 1) {
        __syncthreads();
        int add = (t >= o) ? sh[t - o] : 0;
        __syncthreads();
        sh[t] += add;
    }
    __syncthreads();
    if (i < N_NODES) g_incl[i] = sh[t];
    if (t == SCAN_B - 1) g_bsum[b] = sh[t];
}

__global__ void k_scan2() {
    if (threadIdx.x == 0) {
        int run = 0;
        for (int b = 0; b < NB; b++) { g_boff[b] = run; run += g_bsum[b]; }
    }
}

__global__ void k_scan3() {
    int i = blockIdx.x * 256 + threadIdx.x;
    if (i < N_NODES) {
        int s = g_boff[i >> 10] + g_incl[i] - g_cnt[i];   // exclusive start
        g_rowptr[i] = s;
        g_cur[i] = s;
    }
    if (i == 0) g_rowptr[N_NODES] = N_EDGES;
}

__global__ __launch_bounds__(256) void k_scatter(const int* __restrict__ src,
                                                 const int* __restrict__ dst,
                                                 const int* __restrict__ et) {
    int i = blockIdx.x * 256 + threadIdx.x;
    if (i >= N_EDGES) return;
    int p = atomicAdd(&g_cur[dst[i]], 1);
    g_es[p] = make_int2(src[i], (i << 2) | et[i]);
}

// ---------------- fused softmax + aggregate: one warp per dst node -----------
__global__ __launch_bounds__(256) void k_agg(float* __restrict__ rst,
                                             float* __restrict__ out_a) {
    int d = (blockIdx.x * 256 + threadIdx.x) >> 5;
    int lane = threadIdx.x & 31;
    if (d >= N_NODES) return;
    int start = g_rowptr[d], end = g_rowptr[d + 1];
    float2* rout = (float2*)(rst + (long)d * HD);
    if (start == end) { rout[lane] = make_float2(0.f, 0.f); return; }

    const float*  elf   = (const float*)g_el;
    const float*  erf   = (const float*)g_er;
    const float*  eef   = (const float*)g_ee;
    const float2* feat2 = (const float2*)g_feat;

    // ---- pass 1: z + unnormalized aggregation; lane owns feat cols 2l..2l+1
    int h = lane >> 3;
    float erh = erf[d * 4 + h];
    float ee0 = eef[h], ee1 = eef[4 + h], ee2 = eef[8 + h];
    float z = 0.f;
    float2 acc = make_float2(0.f, 0.f);
    for (int e = start; e < end; e++) {
        int2 m = g_es[e];
        int t = m.y & 3;
        float eet = (t == 0) ? ee0 : ((t == 1) ? ee1 : ee2);
        float sc = elf[m.x * 4 + h] + erh + eet;
        sc = sc > 0.f ? sc : NEG_SLOPE * sc;
        float ev = __expf(sc);
        z += ev;
        float2 f = feat2[(long)m.x * 32 + lane];
        acc.x += f.x * ev;
        acc.y += f.y * ev;
    }
    float invz = 1.0f / z;
    rout[lane] = make_float2(acc.x * invz, acc.y * invz);

    // ---- pass 2: write a; 8 edges per iter, lane = group*4 + head
    int h2 = lane & 3, g = lane >> 2;
    float er2 = erf[d * 4 + h2];
    float f0 = eef[h2], f1 = eef[4 + h2], f2 = eef[8 + h2];
    float invz2 = __shfl_sync(0xffffffffu, invz, h2 << 3);
    for (int e0 = start; e0 < end; e0 += 8) {
        int e = e0 + g;
        if (e < end) {
            int2 m = g_es[e];
            int t = m.y & 3;
            float eet = (t == 0) ? f0 : ((t == 1) ? f1 : f2);
            float sc = elf[m.x * 4 + h2] + er2 + eet;
            sc = sc > 0.f ? sc : NEG_SLOPE * sc;
            out_a[(long)(m.y >> 2) * 4 + h2] = __expf(sc) * invz2;
        }
    }
}

// ---------------- launch ------------------------------------------------------
extern "C" void kernel_launch(void* const* d_in, const int* in_sizes, int n_in,
                              void* d_out, int out_size) {
    const float* x        = (const float*)d_in[0];
    const float* W        = (const float*)d_in[1];
    const float* W_e      = (const float*)d_in[2];
    const float* attn_l   = (const float*)d_in[3];
    const float* attn_r   = (const float*)d_in[4];
    const float* attn_e   = (const float*)d_in[5];
    const float* edge_emb = (const float*)d_in[6];
    const int*   src      = (const int*)d_in[7];
    const int*   dst      = (const int*)d_in[8];
    const int*   et       = (const int*)d_in[9];

    float* rst   = (float*)d_out;
    float* out_a = rst + (long)N_NODES * HD;

    int nb = (N_NODES + 255) / 256;
    int eb = (N_EDGES + 255) / 256;

    k_init<<<nb, 256>>>();
    k_ee<<<1, 384>>>(W_e, attn_e, edge_emb);
    k_gemm<<<(N_NODES + 63) / 64, 256>>>(x, W, attn_l, attn_r);
    k_hist<<<eb, 256>>>(dst);
    k_scan1<<<NB, SCAN_B>>>();
    k_scan2<<<1, 32>>>();
    k_scan3<<<nb, 256>>>();
    k_scatter<<<eb, 256>>>(src, dst, et);
    k_agg<<<(N_NODES * 32 + 255) / 256, 256>>>(rst, out_a);
}